// round 5
// baseline (speedup 1.0000x reference)
#include <cuda_runtime.h>
#include <math.h>

#define BB 16
#define GG 1600
#define DD 2048
#define MM 64
#define WG 40
#define NBLK_VAR (BB * GG / 8)   // 3200 blocks, warp-per-row

// ---- device-global scratch (no allocations allowed) ----
__device__ int   g_flag[BB * GG];
__device__ float g_sums[BB * MM];
__device__ int   g_cnt[BB * MM];
__device__ int   g_done;

// One thread per cell. flag(cell) = parity(mask)? msb(mask) : -1, where mask =
// inside-bits | argmin-bits. (The reference scan's all_free coupling is dead:
// a masked assigned cell always makes all_free false, so each covering box
// simply toggles the cell: -1 -> i, assigned -> -1.)
// grid = 112: blockIdx/7 = batch, blockIdx%7 = 256-cell chunk.
__global__ void __launch_bounds__(256) flags_kernel(const float* __restrict__ bboxes) {
    const int t = threadIdx.x;
    const int gid = blockIdx.x * 256 + t;
    if (gid < BB * MM) g_sums[gid] = 0.0f;
    else if (gid < 2 * BB * MM) g_cnt[gid - BB * MM] = 0;
    else if (gid == 2 * BB * MM) g_done = 0;

    const int b = blockIdx.x / 7;
    const int chunk = blockIdx.x % 7;

    __shared__ float s_corx[MM][4], s_cory[MM][4];
    __shared__ int   s_gmin[MM];

    if (t < MM) {
        const float* bbp = bboxes + ((size_t)b * MM + t) * 7;
        float cx = bbp[0], cy = bbp[1];
        float l = bbp[3], w = bbp[4];
        float ang = bbp[6];
        float rl = fminf(fmaxf(2.56f / l, 1.0f), 6.0f);
        float rw = fminf(fmaxf(2.56f / w, 1.0f), 6.0f);
        float el = l * rl, ew = w * rw;
        float c = cosf(ang), sn = sinf(ang);
        const float cnx[4] = {-0.5f, -0.5f, 0.5f, 0.5f};
        const float cny[4] = {-0.5f,  0.5f, 0.5f, -0.5f};
#pragma unroll
        for (int k = 0; k < 4; k++) {
            float lx = cnx[k] * el, ly = cny[k] * ew;
            s_corx[t][k] = c * lx - sn * ly + cx;
            s_cory[t][k] = sn * lx + c * ly + cy;
        }

        // analytic argmin: 4x4 clamped window around the center contains all
        // fp-rounded tie candidates; lexicographic (d, idx) min with
        // reference-exact rn arithmetic == jnp.argmin first-occurrence.
        float wf = (cx + 51.2f) / 2.56f - 0.5f;
        float hf = (cy + 51.2f) / 2.56f - 0.5f;
        int w0 = min(max((int)floorf(wf) - 1, 0), WG - 4);
        int h0 = min(max((int)floorf(hf) - 1, 0), WG - 4);
        float bd = 3.0e38f;
        int   bg = 1 << 30;
#pragma unroll
        for (int dh = 0; dh < 4; dh++) {
#pragma unroll
            for (int dw = 0; dw < 4; dw++) {
                int hi = h0 + dh, wi = w0 + dw;
                float px = ((float)wi + 0.5f) / 40.0f * 102.4f - 51.2f;
                float py = ((float)hi + 0.5f) / 40.0f * 102.4f - 51.2f;
                float dx = __fsub_rn(px, cx), dy = __fsub_rn(py, cy);
                float d = __fadd_rn(__fmul_rn(dx, dx), __fmul_rn(dy, dy));
                if (d < bd) { bd = d; bg = hi * WG + wi; }
            }
        }
        s_gmin[t] = bg;
    }
    __syncthreads();

    const int cell = chunk * 256 + t;
    if (cell >= GG) return;

    const int wi = cell % WG, hi = cell / WG;
    const float px = ((float)wi + 0.5f) / 40.0f * 102.4f - 51.2f;
    const float py = ((float)hi + 0.5f) / 40.0f * 102.4f - 51.2f;

    unsigned long long m = 0ull;
#pragma unroll 4
    for (int i = 0; i < MM; i++) {
        const float x0 = s_corx[i][0], y0 = s_cory[i][0];
        const float x1 = s_corx[i][1], y1 = s_cory[i][1];
        const float x2 = s_corx[i][2], y2 = s_cory[i][2];
        const float x3 = s_corx[i][3], y3 = s_cory[i][3];
        const float e0x = x1 - x0, e0y = y1 - y0;
        const float e1x = x2 - x1, e1y = y2 - y1;
        const float e2x = x3 - x2, e2y = y3 - y2;
        const float e3x = x0 - x3, e3y = y0 - y3;
        float c0 = e0x * (py - y0) - e0y * (px - x0);
        float c1 = e1x * (py - y1) - e1y * (px - x1);
        float c2 = e2x * (py - y2) - e2y * (px - x2);
        float c3 = e3x * (py - y3) - e3y * (px - x3);
        bool allpos = (c0 >= 0.0f) & (c1 >= 0.0f) & (c2 >= 0.0f) & (c3 >= 0.0f);
        bool allneg = (c0 <= 0.0f) & (c1 <= 0.0f) & (c2 <= 0.0f) & (c3 <= 0.0f);
        bool ins = (allpos | allneg) | (s_gmin[i] == cell);
        if (ins) m |= (1ull << i);
    }
    g_flag[b * GG + cell] = (__popcll(m) & 1) ? (63 - __clzll(m)) : -1;
}

// Warp-per-row variance (MLP=16) + direct gather into per-(batch,box)
// accumulators. Release/acquire protocol is minimal: only the 8 lane-0
// threads (the ones that issued the accumulator atomics) fence; one ticket
// atomic per block; last block acquire-fences and reduces.
__global__ void __launch_bounds__(256) var_gather_kernel(const float* __restrict__ atten,
                                                         float* __restrict__ out) {
    const int t = threadIdx.x;
    const int row  = blockIdx.x * 8 + (t >> 5);
    const int lane = t & 31;
    const float4* p = reinterpret_cast<const float4*>(atten) + (size_t)row * (DD / 4);

    // shift by 0.5 (inputs U[0,1]) to kill cancellation in sumsq - sum^2/n
    float sa = 0.0f, sb = 0.0f, qa = 0.0f, qb = 0.0f;
#pragma unroll
    for (int j = 0; j < 16; j++) {
        float4 v = __ldcs(p + lane + 32 * j);
        float a0 = v.x - 0.5f, a1 = v.y - 0.5f, a2 = v.z - 0.5f, a3 = v.w - 0.5f;
        sa += a0; sb += a1; sa += a2; sb += a3;
        qa = fmaf(a0, a0, qa); qb = fmaf(a1, a1, qb);
        qa = fmaf(a2, a2, qa); qb = fmaf(a3, a3, qb);
    }
    float s = sa + sb, s2 = qa + qb;
#pragma unroll
    for (int o = 16; o > 0; o >>= 1) {
        s  += __shfl_xor_sync(0xFFFFFFFFu, s,  o);
        s2 += __shfl_xor_sync(0xFFFFFFFFu, s2, o);
    }

    if (lane == 0) {
        float var = (s2 - s * s / (float)DD) / (float)(DD - 1);
        int f = g_flag[row];
        if (f >= 0) {
            int b = row / GG;
            atomicAdd(&g_sums[b * MM + f], var);
            atomicAdd(&g_cnt[b * MM + f], 1);
        }
        __threadfence();   // release: order THIS thread's atomics (8/block)
    }
    __syncthreads();
    __shared__ int s_tk;
    if (t == 0) s_tk = atomicAdd(&g_done, 1);
    __syncthreads();
    if (s_tk == NBLK_VAR - 1 && t < 32) {
        __threadfence();   // acquire
        float loss = 0.0f;
        int   pos  = 0;
        for (int j = t; j < BB * MM; j += 32) {
            int   c  = __ldcg(&g_cnt[j]);
            float sm = __ldcg(&g_sums[j]);
            if (c > 0) { loss += sm / (float)c; pos++; }
        }
#pragma unroll
        for (int o = 16; o > 0; o >>= 1) {
            loss += __shfl_xor_sync(0xFFFFFFFFu, loss, o);
            pos  += __shfl_xor_sync(0xFFFFFFFFu, pos,  o);
        }
        if (t == 0) {
            if (pos < 1) pos = 1;
            out[0] = -loss / (float)pos;
        }
    }
}

extern "C" void kernel_launch(void* const* d_in, const int* in_sizes, int n_in,
                              void* d_out, int out_size) {
    const float* atten = (const float*)d_in[0];   // (16, 1600, 2048) fp32
    const float* bbox  = (const float*)d_in[1];   // (16, 64, 7) fp32
    float* out = (float*)d_out;

    flags_kernel<<<7 * BB, 256>>>(bbox);
    var_gather_kernel<<<NBLK_VAR, 256>>>(atten, out);
}

// round 6
// speedup vs baseline: 1.0479x; 1.0479x over previous
#include <cuda_runtime.h>
#include <math.h>

#define BB 16
#define GG 1600
#define DD 2048
#define MM 64
#define WG 40
#define NBLK_VAR (BB * GG)   // block-per-row: 25600 blocks

// ---- device-global scratch (no allocations allowed) ----
__device__ int   g_flag[BB * GG];
__device__ float g_sums[BB * MM];
__device__ int   g_cnt[BB * MM];
__device__ int   g_done;

// One thread per cell. flag(cell) = parity(mask)? msb(mask) : -1, where mask =
// inside-bits | argmin-bits. (The reference scan's all_free coupling is dead:
// a masked assigned cell always makes all_free false, so each covering box
// simply toggles the cell: -1 -> i, assigned -> -1.)
// grid = 112: blockIdx/7 = batch, blockIdx%7 = 256-cell chunk.
__global__ void __launch_bounds__(256) flags_kernel(const float* __restrict__ bboxes) {
    const int t = threadIdx.x;
    const int gid = blockIdx.x * 256 + t;
    if (gid < BB * MM) g_sums[gid] = 0.0f;
    else if (gid < 2 * BB * MM) g_cnt[gid - BB * MM] = 0;
    else if (gid == 2 * BB * MM) g_done = 0;

    const int b = blockIdx.x / 7;
    const int chunk = blockIdx.x % 7;

    __shared__ float s_corx[MM][4], s_cory[MM][4];
    __shared__ int   s_gmin[MM];

    if (t < MM) {
        const float* bbp = bboxes + ((size_t)b * MM + t) * 7;
        float cx = bbp[0], cy = bbp[1];
        float l = bbp[3], w = bbp[4];
        float ang = bbp[6];
        float rl = fminf(fmaxf(2.56f / l, 1.0f), 6.0f);
        float rw = fminf(fmaxf(2.56f / w, 1.0f), 6.0f);
        float el = l * rl, ew = w * rw;
        float c = cosf(ang), sn = sinf(ang);
        const float cnx[4] = {-0.5f, -0.5f, 0.5f, 0.5f};
        const float cny[4] = {-0.5f,  0.5f, 0.5f, -0.5f};
#pragma unroll
        for (int k = 0; k < 4; k++) {
            float lx = cnx[k] * el, ly = cny[k] * ew;
            s_corx[t][k] = c * lx - sn * ly + cx;
            s_cory[t][k] = sn * lx + c * ly + cy;
        }

        // analytic argmin: 4x4 clamped window around the center contains all
        // fp-rounded tie candidates; lexicographic (d, idx) min with
        // reference-exact rn arithmetic == jnp.argmin first-occurrence.
        float wf = (cx + 51.2f) / 2.56f - 0.5f;
        float hf = (cy + 51.2f) / 2.56f - 0.5f;
        int w0 = min(max((int)floorf(wf) - 1, 0), WG - 4);
        int h0 = min(max((int)floorf(hf) - 1, 0), WG - 4);
        float bd = 3.0e38f;
        int   bg = 1 << 30;
#pragma unroll
        for (int dh = 0; dh < 4; dh++) {
#pragma unroll
            for (int dw = 0; dw < 4; dw++) {
                int hi = h0 + dh, wi = w0 + dw;
                float px = ((float)wi + 0.5f) / 40.0f * 102.4f - 51.2f;
                float py = ((float)hi + 0.5f) / 40.0f * 102.4f - 51.2f;
                float dx = __fsub_rn(px, cx), dy = __fsub_rn(py, cy);
                float d = __fadd_rn(__fmul_rn(dx, dx), __fmul_rn(dy, dy));
                if (d < bd) { bd = d; bg = hi * WG + wi; }
            }
        }
        s_gmin[t] = bg;
    }
    __syncthreads();

    const int cell = chunk * 256 + t;
    if (cell >= GG) return;

    const int wi = cell % WG, hi = cell / WG;
    const float px = ((float)wi + 0.5f) / 40.0f * 102.4f - 51.2f;
    const float py = ((float)hi + 0.5f) / 40.0f * 102.4f - 51.2f;

    unsigned long long m = 0ull;
#pragma unroll 4
    for (int i = 0; i < MM; i++) {
        const float x0 = s_corx[i][0], y0 = s_cory[i][0];
        const float x1 = s_corx[i][1], y1 = s_cory[i][1];
        const float x2 = s_corx[i][2], y2 = s_cory[i][2];
        const float x3 = s_corx[i][3], y3 = s_cory[i][3];
        const float e0x = x1 - x0, e0y = y1 - y0;
        const float e1x = x2 - x1, e1y = y2 - y1;
        const float e2x = x3 - x2, e2y = y3 - y2;
        const float e3x = x0 - x3, e3y = y0 - y3;
        float c0 = e0x * (py - y0) - e0y * (px - x0);
        float c1 = e1x * (py - y1) - e1y * (px - x1);
        float c2 = e2x * (py - y2) - e2y * (px - x2);
        float c3 = e3x * (py - y3) - e3y * (px - x3);
        bool allpos = (c0 >= 0.0f) & (c1 >= 0.0f) & (c2 >= 0.0f) & (c3 >= 0.0f);
        bool allneg = (c0 <= 0.0f) & (c1 <= 0.0f) & (c2 <= 0.0f) & (c3 <= 0.0f);
        bool ins = (allpos | allneg) | (s_gmin[i] == cell);
        if (ins) m |= (1ull << i);
    }
    g_flag[b * GG + cell] = (__popcll(m) & 1) ? (63 - __clzll(m)) : -1;
}

// Block-per-row variance (the empirically 74.5%-DRAM load shape: 2 front-
// batched LDG.128 per thread, low L1tex queue pressure) + per-row gather by
// thread 0 + last-block parallel finalize.
__global__ void __launch_bounds__(256) var_gather_kernel(const float* __restrict__ atten,
                                                         float* __restrict__ out) {
    const int row = blockIdx.x;
    const int t = threadIdx.x;
    const float4* p = reinterpret_cast<const float4*>(atten) + (size_t)row * (DD / 4);

    // shift by 0.5 (inputs U[0,1]) to kill cancellation in sumsq - sum^2/n
    float s = 0.0f, s2 = 0.0f;
#pragma unroll
    for (int k = 0; k < 2; k++) {
        float4 v = p[t + k * 256];
        float a0 = v.x - 0.5f, a1 = v.y - 0.5f, a2 = v.z - 0.5f, a3 = v.w - 0.5f;
        s += a0; s += a1; s += a2; s += a3;
        s2 = fmaf(a0, a0, s2);
        s2 = fmaf(a1, a1, s2);
        s2 = fmaf(a2, a2, s2);
        s2 = fmaf(a3, a3, s2);
    }
#pragma unroll
    for (int o = 16; o > 0; o >>= 1) {
        s  += __shfl_xor_sync(0xFFFFFFFFu, s,  o);
        s2 += __shfl_xor_sync(0xFFFFFFFFu, s2, o);
    }
    __shared__ float sh[8], sh2[8];
    __shared__ int s_tk;
    if ((t & 31) == 0) { sh[t >> 5] = s; sh2[t >> 5] = s2; }
    __syncthreads();
    if (t == 0) {
        float S = 0.0f, S2 = 0.0f;
#pragma unroll
        for (int i = 0; i < 8; i++) { S += sh[i]; S2 += sh2[i]; }
        float var = (S2 - S * S / (float)DD) / (float)(DD - 1);
        int f = g_flag[row];
        if (f >= 0) {
            int b = row / GG;
            atomicAdd(&g_sums[b * MM + f], var);
            atomicAdd(&g_cnt[b * MM + f], 1);
        }
        __threadfence();   // release this block's accumulator atomics
        s_tk = atomicAdd(&g_done, 1);
    }
    __syncthreads();
    if (s_tk == NBLK_VAR - 1) {
        // last block: acquire + parallel finalize over 1024 (b,box) entries
        __threadfence();
        float loss = 0.0f;
        int   pos  = 0;
#pragma unroll
        for (int k = 0; k < 4; k++) {
            int j = t + k * 256;
            int   c  = __ldcg(&g_cnt[j]);
            float sm = __ldcg(&g_sums[j]);
            if (c > 0) { loss += sm / (float)c; pos++; }
        }
#pragma unroll
        for (int o = 16; o > 0; o >>= 1) {
            loss += __shfl_xor_sync(0xFFFFFFFFu, loss, o);
            pos  += __shfl_xor_sync(0xFFFFFFFFu, pos,  o);
        }
        __shared__ float shl[8];
        __shared__ int   shp[8];
        if ((t & 31) == 0) { shl[t >> 5] = loss; shp[t >> 5] = pos; }
        __syncthreads();
        if (t == 0) {
            float L = 0.0f; int P = 0;
#pragma unroll
            for (int i = 0; i < 8; i++) { L += shl[i]; P += shp[i]; }
            if (P < 1) P = 1;
            out[0] = -L / (float)P;
        }
    }
}

extern "C" void kernel_launch(void* const* d_in, const int* in_sizes, int n_in,
                              void* d_out, int out_size) {
    const float* atten = (const float*)d_in[0];   // (16, 1600, 2048) fp32
    const float* bbox  = (const float*)d_in[1];   // (16, 64, 7) fp32
    float* out = (float*)d_out;

    flags_kernel<<<7 * BB, 256>>>(bbox);
    var_gather_kernel<<<NBLK_VAR, 256>>>(atten, out);
}

// round 7
// speedup vs baseline: 1.3402x; 1.2790x over previous
#include <cuda_runtime.h>
#include <math.h>

#define BB 16
#define GG 1600
#define DD 2048
#define MM 64
#define WG 40

// ---- device-global scratch (no allocations allowed) ----
__device__ int   g_flag[BB * GG];
__device__ float g_sums[BB * MM];
__device__ int   g_cnt[BB * MM];

// One thread per cell. flag(cell) = parity(mask)? msb(mask) : -1, where mask =
// inside-bits | argmin-bits. (The reference scan's all_free coupling is dead:
// a masked assigned cell always makes all_free false, so each covering box
// simply toggles the cell: -1 -> i, assigned -> -1.)
// grid = 112: blockIdx/7 = batch, blockIdx%7 = 256-cell chunk.
__global__ void __launch_bounds__(256) flags_kernel(const float* __restrict__ bboxes) {
    const int t = threadIdx.x;
    const int gid = blockIdx.x * 256 + t;
    if (gid < BB * MM) g_sums[gid] = 0.0f;
    else if (gid < 2 * BB * MM) g_cnt[gid - BB * MM] = 0;

    const int b = blockIdx.x / 7;
    const int chunk = blockIdx.x % 7;

    __shared__ float s_corx[MM][4], s_cory[MM][4];
    __shared__ int   s_gmin[MM];

    if (t < MM) {
        const float* bbp = bboxes + ((size_t)b * MM + t) * 7;
        float cx = bbp[0], cy = bbp[1];
        float l = bbp[3], w = bbp[4];
        float ang = bbp[6];
        float rl = fminf(fmaxf(2.56f / l, 1.0f), 6.0f);
        float rw = fminf(fmaxf(2.56f / w, 1.0f), 6.0f);
        float el = l * rl, ew = w * rw;
        float c = cosf(ang), sn = sinf(ang);
        const float cnx[4] = {-0.5f, -0.5f, 0.5f, 0.5f};
        const float cny[4] = {-0.5f,  0.5f, 0.5f, -0.5f};
#pragma unroll
        for (int k = 0; k < 4; k++) {
            float lx = cnx[k] * el, ly = cny[k] * ew;
            s_corx[t][k] = c * lx - sn * ly + cx;
            s_cory[t][k] = sn * lx + c * ly + cy;
        }

        // analytic argmin: 4x4 clamped window around the center contains all
        // fp-rounded tie candidates; lexicographic (d, idx) min with
        // reference-exact rn arithmetic == jnp.argmin first-occurrence.
        float wf = (cx + 51.2f) / 2.56f - 0.5f;
        float hf = (cy + 51.2f) / 2.56f - 0.5f;
        int w0 = min(max((int)floorf(wf) - 1, 0), WG - 4);
        int h0 = min(max((int)floorf(hf) - 1, 0), WG - 4);
        float bd = 3.0e38f;
        int   bg = 1 << 30;
#pragma unroll
        for (int dh = 0; dh < 4; dh++) {
#pragma unroll
            for (int dw = 0; dw < 4; dw++) {
                int hi = h0 + dh, wi = w0 + dw;
                float px = ((float)wi + 0.5f) / 40.0f * 102.4f - 51.2f;
                float py = ((float)hi + 0.5f) / 40.0f * 102.4f - 51.2f;
                float dx = __fsub_rn(px, cx), dy = __fsub_rn(py, cy);
                float d = __fadd_rn(__fmul_rn(dx, dx), __fmul_rn(dy, dy));
                if (d < bd) { bd = d; bg = hi * WG + wi; }
            }
        }
        s_gmin[t] = bg;
    }
    __syncthreads();

    const int cell = chunk * 256 + t;
    if (cell >= GG) return;

    const int wi = cell % WG, hi = cell / WG;
    const float px = ((float)wi + 0.5f) / 40.0f * 102.4f - 51.2f;
    const float py = ((float)hi + 0.5f) / 40.0f * 102.4f - 51.2f;

    unsigned long long m = 0ull;
#pragma unroll 4
    for (int i = 0; i < MM; i++) {
        const float x0 = s_corx[i][0], y0 = s_cory[i][0];
        const float x1 = s_corx[i][1], y1 = s_cory[i][1];
        const float x2 = s_corx[i][2], y2 = s_cory[i][2];
        const float x3 = s_corx[i][3], y3 = s_cory[i][3];
        const float e0x = x1 - x0, e0y = y1 - y0;
        const float e1x = x2 - x1, e1y = y2 - y1;
        const float e2x = x3 - x2, e2y = y3 - y2;
        const float e3x = x0 - x3, e3y = y0 - y3;
        float c0 = e0x * (py - y0) - e0y * (px - x0);
        float c1 = e1x * (py - y1) - e1y * (px - x1);
        float c2 = e2x * (py - y2) - e2y * (px - x2);
        float c3 = e3x * (py - y3) - e3y * (px - x3);
        bool allpos = (c0 >= 0.0f) & (c1 >= 0.0f) & (c2 >= 0.0f) & (c3 >= 0.0f);
        bool allneg = (c0 <= 0.0f) & (c1 <= 0.0f) & (c2 <= 0.0f) & (c3 <= 0.0f);
        bool ins = (allpos | allneg) | (s_gmin[i] == cell);
        if (ins) m |= (1ull << i);
    }
    g_flag[b * GG + cell] = (__popcll(m) & 1) ? (63 - __clzll(m)) : -1;
}

// Block-per-row variance (the R2 shape that measured 74.5% DRAM) with a
// minimal epilogue: t0 computes var, loads its flag, and issues two L2
// atomics. NO fence, NO ticket, NO L1 flush — cross-kernel ordering comes
// from the launch boundary.
__global__ void __launch_bounds__(256) var_gather_kernel(const float* __restrict__ atten) {
    const int row = blockIdx.x;
    const int t = threadIdx.x;
    const float4* p = reinterpret_cast<const float4*>(atten) + (size_t)row * (DD / 4);

    // shift by 0.5 (inputs U[0,1]) to kill cancellation in sumsq - sum^2/n
    float s = 0.0f, s2 = 0.0f;
#pragma unroll
    for (int k = 0; k < 2; k++) {
        float4 v = p[t + k * 256];
        float a0 = v.x - 0.5f, a1 = v.y - 0.5f, a2 = v.z - 0.5f, a3 = v.w - 0.5f;
        s += a0; s += a1; s += a2; s += a3;
        s2 = fmaf(a0, a0, s2);
        s2 = fmaf(a1, a1, s2);
        s2 = fmaf(a2, a2, s2);
        s2 = fmaf(a3, a3, s2);
    }
#pragma unroll
    for (int o = 16; o > 0; o >>= 1) {
        s  += __shfl_xor_sync(0xFFFFFFFFu, s,  o);
        s2 += __shfl_xor_sync(0xFFFFFFFFu, s2, o);
    }
    __shared__ float sh[8], sh2[8];
    if ((t & 31) == 0) { sh[t >> 5] = s; sh2[t >> 5] = s2; }
    __syncthreads();
    if (t == 0) {
        float S = 0.0f, S2 = 0.0f;
#pragma unroll
        for (int i = 0; i < 8; i++) { S += sh[i]; S2 += sh2[i]; }
        float var = (S2 - S * S / (float)DD) / (float)(DD - 1);
        int f = g_flag[row];
        if (f >= 0) {
            int b = row / GG;
            atomicAdd(&g_sums[b * MM + f], var);
            atomicAdd(&g_cnt[b * MM + f], 1);
        }
    }
}

// Single block: reduce the 1024 (batch,box) accumulators into the loss.
__global__ void __launch_bounds__(256) finalize_kernel(float* __restrict__ out) {
    const int t = threadIdx.x;
    float loss = 0.0f;
    int   pos  = 0;
#pragma unroll
    for (int k = 0; k < 4; k++) {
        int j = t + k * 256;
        int   c  = g_cnt[j];
        float sm = g_sums[j];
        if (c > 0) { loss += sm / (float)c; pos++; }
    }
#pragma unroll
    for (int o = 16; o > 0; o >>= 1) {
        loss += __shfl_xor_sync(0xFFFFFFFFu, loss, o);
        pos  += __shfl_xor_sync(0xFFFFFFFFu, pos,  o);
    }
    __shared__ float shl[8];
    __shared__ int   shp[8];
    if ((t & 31) == 0) { shl[t >> 5] = loss; shp[t >> 5] = pos; }
    __syncthreads();
    if (t == 0) {
        float L = 0.0f; int P = 0;
#pragma unroll
        for (int i = 0; i < 8; i++) { L += shl[i]; P += shp[i]; }
        if (P < 1) P = 1;
        out[0] = -L / (float)P;
    }
}

extern "C" void kernel_launch(void* const* d_in, const int* in_sizes, int n_in,
                              void* d_out, int out_size) {
    const float* atten = (const float*)d_in[0];   // (16, 1600, 2048) fp32
    const float* bbox  = (const float*)d_in[1];   // (16, 64, 7) fp32
    float* out = (float*)d_out;

    flags_kernel<<<7 * BB, 256>>>(bbox);
    var_gather_kernel<<<BB * GG, 256>>>(atten);
    finalize_kernel<<<1, 256>>>(out);
}